// round 16
// baseline (speedup 1.0000x reference)
#include <cuda_runtime.h>
#include <cuda_bf16.h>
#include <math.h>

// Problem constants
#define BATCH   512
#define DIM     256
#define NTREES  512
#define DEPTH   6
#define UNITS   3
#define NLEAVES 64
#define NCOLS   (NTREES * DEPTH)   // 3072 sparsemax columns
#define MAXC    64                 // max sparsemax support per column (padded)
#define BT      64                 // forest batch tile (2 b per thread, packed f32x2)
#define NT      8                  // forest tree tile

// ---- packed fp32x2 helpers (sm_103a FFMA2 path, PTX-only) ----
// 64-bit integer carrier type so the "l" asm constraint matches.
typedef unsigned long long f32x2;
__device__ __forceinline__ f32x2 pk2(float a, float b) {
    f32x2 r; asm("mov.b64 %0,{%1,%2};" : "=l"(r) : "f"(a), "f"(b)); return r;
}
__device__ __forceinline__ void upk2(float& a, float& b, f32x2 v) {
    asm("mov.b64 {%0,%1},%2;" : "=f"(a), "=f"(b) : "l"(v));
}
__device__ __forceinline__ f32x2 mul2(f32x2 a, f32x2 b) {
    f32x2 r; asm("mul.rn.f32x2 %0,%1,%2;" : "=l"(r) : "l"(a), "l"(b)); return r;
}
__device__ __forceinline__ f32x2 fma2(f32x2 a, f32x2 b, f32x2 c) {
    f32x2 r; asm("fma.rn.f32x2 %0,%1,%2,%3;" : "=l"(r) : "l"(a), "l"(b), "l"(c)); return r;
}
struct f32x2x2 { f32x2 x, y; };

// -------- device scratch (no dynamic allocation allowed) --------
__device__ float  g_xT[DIM * BATCH];       // transposed x: (DIM, BATCH)
__device__ float  g_fslT[NCOLS * DIM];     // transposed fsl: (col, i)
__device__ int    g_nnz[NCOLS];            // PADDED support size (multiple of 2)
__device__ float2 g_sel[NCOLS * MAXC];     // interleaved (idx*BATCH as int bits, weight)
__device__ float  g_gate[NCOLS * BATCH];   // gate values, layout (col, b)

// ============================================================================
// Kernel 0: float4 tiled transposes. 32x32 tiles, 256 threads, conflict-free.
//  blocks [0, 768): fsl (256 i, 3072 col) -> fslT (col, i).
//  blocks [768, 896): x (512 b, 256 i)    -> xT (i, b).
// ============================================================================
__global__ void __launch_bounds__(256)
transpose_kernel(const float* __restrict__ x,
                 const float* __restrict__ fsl)
{
    __shared__ float s[32][33];
    const int bid = blockIdx.x;
    const int t   = threadIdx.x;
    const int row = t >> 3;
    const int c4  = t & 7;

    const float* src;
    float*       dst;
    int src_stride, dst_stride, r0_in, c0_in;

    if (bid < 768) {
        const int it = bid / 96;
        const int ct = bid % 96;
        src = fsl;   src_stride = NCOLS;  r0_in = it * 32; c0_in = ct * 32;
        dst = g_fslT; dst_stride = DIM;
    } else {
        const int tt = bid - 768;
        const int bt = tt & 15;
        const int it = tt >> 4;
        src = x;     src_stride = DIM;    r0_in = bt * 32; c0_in = it * 32;
        dst = g_xT;  dst_stride = BATCH;
    }

    float4 v = *(const float4*)(src + (size_t)(r0_in + row) * src_stride + c0_in + c4 * 4);
    s[row][c4 * 4 + 0] = v.x;
    s[row][c4 * 4 + 1] = v.y;
    s[row][c4 * 4 + 2] = v.z;
    s[row][c4 * 4 + 3] = v.w;
    __syncthreads();

    float4 w;
    w.x = s[c4 * 4 + 0][row];
    w.y = s[c4 * 4 + 1][row];
    w.z = s[c4 * 4 + 2][row];
    w.w = s[c4 * 4 + 3][row];
    *(float4*)(dst + (size_t)(c0_in + row) * dst_stride + r0_in + c4 * 4) = w;
}

// ============================================================================
// Kernel 1: sparsemax, one warp per column, coalesced fslT loads.
// Michelot warm-started at tau0 = max(z)-1. Output padded to multiple of 2.
// ============================================================================
__global__ void __launch_bounds__(256)
sparsemax_kernel()
{
    const int warp = threadIdx.x >> 5;
    const int lane = threadIdx.x & 31;
    const int col  = blockIdx.x * 8 + warp;

    float z[8];
    #pragma unroll
    for (int j = 0; j < 8; j++)
        z[j] = g_fslT[col * DIM + j * 32 + lane];

    float m = z[0];
    #pragma unroll
    for (int j = 1; j < 8; j++) m = fmaxf(m, z[j]);
    #pragma unroll
    for (int o = 16; o > 0; o >>= 1)
        m = fmaxf(m, __shfl_xor_sync(0xffffffffu, m, o));
    float tau = m - 1.0f;

    int k_prev = -1;
    #pragma unroll 1
    for (int it = 0; it < 16; it++) {
        float s = 0.0f;
        int   k = 0;
        #pragma unroll
        for (int j = 0; j < 8; j++)
            if (z[j] > tau) { s += z[j]; k++; }
        #pragma unroll
        for (int o = 16; o > 0; o >>= 1)
            s += __shfl_xor_sync(0xffffffffu, s, o);
        k = __reduce_add_sync(0xffffffffu, k);
        if (k == k_prev) break;
        k_prev = k;
        tau = (s - 1.0f) / (float)k;
    }

    int base = 0;
    #pragma unroll
    for (int j = 0; j < 8; j++) {
        const bool nz = (z[j] > tau);
        const unsigned mm = __ballot_sync(0xffffffffu, nz);
        if (nz) {
            int pos = base + __popc(mm & ((1u << lane) - 1u));
            if (pos < MAXC)
                g_sel[col * MAXC + pos] =
                    make_float2(__int_as_float((j * 32 + lane) * BATCH), z[j] - tau);
        }
        base += __popc(mm);
    }
    if (base > MAXC) base = MAXC;
    const int pad = (base + 1) & ~1;
    if (lane < pad - base)
        g_sel[col * MAXC + base + lane] = make_float2(__int_as_float(0), 0.0f);
    if (lane == 0) g_nnz[col] = pad;
}

// ============================================================================
// Kernel 2: gate[col][b] = sparsemoid((sum_j w_j*xT[idx_j][b] - th)*e^{-lt}).
// One block per column; thread owns b = 2*tid, 2*tid+1 -> float2 LDG/STG.
// ============================================================================
__global__ void __launch_bounds__(256)
fv_kernel(const float* __restrict__ th,
          const float* __restrict__ lt)
{
    const int col = blockIdx.x;
    const int tid = threadIdx.x;
    const int cnt = g_nnz[col];           // multiple of 2
    const float2* __restrict__ lst = g_sel + col * MAXC;

    const float thv = __ldg(th + col);
    const float etv = __expf(-__ldg(lt + col));

    float f0 = 0.0f, f1 = 0.0f;
    #pragma unroll 1
    for (int j = 0; j < cnt; j += 2) {
        float2 e0 = __ldg(lst + j);
        float2 e1 = __ldg(lst + j + 1);
        float2 a = *(const float2*)(g_xT + __float_as_int(e0.x) + 2 * tid);
        float2 b = *(const float2*)(g_xT + __float_as_int(e1.x) + 2 * tid);
        f0 += e0.y * a.x + e1.y * b.x;
        f1 += e0.y * a.y + e1.y * b.y;
    }
    float2 gv;
    gv.x = __saturatef(0.5f * ((f0 - thv) * etv) + 0.5f);
    gv.y = __saturatef(0.5f * ((f1 - thv) * etv) + 0.5f);
    *(float2*)(g_gate + col * BATCH + 2 * tid) = gv;
}

// ============================================================================
// Kernel 3: tiled forest, 2 batch rows per thread PACKED as f32x2.
// Block = (64-b x 8-n) tile; 512 blocks x 256 threads.
// resp pre-duplicated in smem as (v,v) f32x2 pairs -> each 16B LDS yields
// 2 packed operands; contraction runs on FFMA2 (half the FMA instrs).
// ============================================================================
__global__ void __launch_bounds__(256, 4)
forest_kernel(const float* __restrict__ resp,  // (NTREES, UNITS, NLEAVES)
              float* __restrict__ out)         // (BATCH, NTREES, UNITS)
{
    const int nt  = blockIdx.x & 63;      // 64 n-tiles
    const int btl = blockIdx.x >> 6;      // 8 b-tiles
    const int n0  = nt * NT;
    const int b0  = btl * BT;
    const int tid = threadIdx.x;
    const int tx  = tid & 31;             // b_local (first of packed pair)
    const int ty  = tid >> 5;             // n_local, 0..7

    const int b1 = b0 + tx;
    const int n  = n0 + ty;

    // issue gate loads first (independent of smem staging), pack (b, b+32)
    float ga[DEPTH], gb[DEPTH];
    #pragma unroll
    for (int d = 0; d < DEPTH; d++) {
        ga[d] = g_gate[(n * DEPTH + d) * BATCH + b1];
        gb[d] = g_gate[(n * DEPTH + d) * BATCH + b1 + 32];
    }

    __shared__ f32x2x2 s_r2[NT * 96];             // resp dup: 8 trees x 192 f32x2 = 12 KB
    __shared__ float   s_out[BT][NT * UNITS + 1]; // 64 x 25, conflict-free

    // stage resp, duplicating each value into both f32x2 lanes
    {
        #pragma unroll
        for (int r = 0; r < 2; r++) {
            int f = tid + r * 256;                // float4 index 0..383
            if (f < NT * 48) {
                float4 v = ((const float4*)resp)[n0 * 48 + f];
                f32x2x2 w0; w0.x = pk2(v.x, v.x); w0.y = pk2(v.y, v.y);
                f32x2x2 w1; w1.x = pk2(v.z, v.z); w1.y = pk2(v.w, v.w);
                s_r2[2 * f]     = w0;
                s_r2[2 * f + 1] = w1;
            }
        }
    }
    __syncthreads();

    // packed gates and complements
    const f32x2 ONE2  = pk2(1.0f, 1.0f);
    const f32x2 MONE2 = pk2(-1.0f, -1.0f);
    f32x2 g2[DEPTH], og2[DEPTH];
    #pragma unroll
    for (int d = 0; d < DEPTH; d++) {
        g2[d]  = pk2(ga[d], gb[d]);
        og2[d] = fma2(g2[d], MONE2, ONE2);        // 1 - g
    }

    // packed leaf factorization: p_c = qlo[c&7] * qhi[c>>3]
    f32x2 ql2[8], qh2[8];
    #pragma unroll
    for (int c = 0; c < 8; c++) {
        f32x2 p0 = (c & 1) ? og2[0] : g2[0];
        f32x2 p1 = (c & 2) ? og2[1] : g2[1];
        f32x2 p2 = (c & 4) ? og2[2] : g2[2];
        ql2[c] = mul2(mul2(p0, p1), p2);
        f32x2 p3 = (c & 1) ? og2[3] : g2[3];
        f32x2 p4 = (c & 2) ? og2[4] : g2[4];
        f32x2 p5 = (c & 4) ? og2[5] : g2[5];
        qh2[c] = mul2(mul2(p3, p4), p5);
    }

    // packed response contraction
    const f32x2x2* rr = s_r2 + ty * 96;
    f32x2 acc2[UNITS];
    #pragma unroll
    for (int u = 0; u < UNITS; u++) acc2[u] = pk2(0.0f, 0.0f);

    #pragma unroll
    for (int hi = 0; hi < 8; hi++) {
        #pragma unroll
        for (int u = 0; u < UNITS; u++) {
            const int pb = u * 32 + hi * 4;       // f32x2x2 base
            f32x2x2 p0 = rr[pb + 0];
            f32x2x2 p1 = rr[pb + 1];
            f32x2x2 p2 = rr[pb + 2];
            f32x2x2 p3 = rr[pb + 3];
            f32x2 t = mul2(p0.x, ql2[0]);
            t = fma2(p0.y, ql2[1], t);
            t = fma2(p1.x, ql2[2], t);
            t = fma2(p1.y, ql2[3], t);
            t = fma2(p2.x, ql2[4], t);
            t = fma2(p2.y, ql2[5], t);
            t = fma2(p3.x, ql2[6], t);
            t = fma2(p3.y, ql2[7], t);
            acc2[u] = fma2(qh2[hi], t, acc2[u]);
        }
    }

    #pragma unroll
    for (int u = 0; u < UNITS; u++) {
        float a, b;
        upk2(a, b, acc2[u]);
        s_out[tx][ty * UNITS + u]      = a;
        s_out[tx + 32][ty * UNITS + u] = b;
    }
    __syncthreads();

    // coalesced write-out: per-b contiguous 24-float (96 B) runs
    #pragma unroll
    for (int r = 0; r < 6; r++) {
        int i   = tid + r * 256;                 // 0 .. 1535
        int row = i / (NT * UNITS);              // b_local 0..63
        int c   = i % (NT * UNITS);
        out[(size_t)(b0 + row) * (NTREES * UNITS) + n0 * UNITS + c] = s_out[row][c];
    }
}

// ============================================================================
extern "C" void kernel_launch(void* const* d_in, const int* in_sizes, int n_in,
                              void* d_out, int out_size)
{
    const float* x    = (const float*)d_in[0];  // (512, 256)
    const float* fsl  = (const float*)d_in[1];  // (256, 512, 6)
    const float* th   = (const float*)d_in[2];  // (512, 6)
    const float* lt   = (const float*)d_in[3];  // (512, 6)
    const float* resp = (const float*)d_in[4];  // (512, 3, 64)
    float* out = (float*)d_out;                 // (512, 512, 3)

    transpose_kernel<<<896, 256>>>(x, fsl);
    sparsemax_kernel<<<NCOLS / 8, 256>>>();
    fv_kernel<<<NCOLS, 256>>>(th, lt);
    forest_kernel<<<(BATCH / BT) * (NTREES / NT), 256>>>(resp, out);
}